// round 8
// baseline (speedup 1.0000x reference)
#include <cuda_runtime.h>
#include <cuda_bf16.h>

#define HDIM 16
#define UDIM 7
#define HID  64
#define XDIM 23
#define CHUNK 512
#define NTHREADS 128

__device__ __forceinline__ unsigned smem_u32(const void* p) {
    return (unsigned)__cvta_generic_to_shared(p);
}
__device__ __forceinline__ void cp16(unsigned dst, const void* src) {
    asm volatile("cp.async.cg.shared.global [%0], [%1], 16;" :: "r"(dst), "l"(src));
}
__device__ __forceinline__ void cp4(unsigned dst, const void* src) {
    asm volatile("cp.async.ca.shared.global [%0], [%1], 4;" :: "r"(dst), "l"(src));
}
__device__ __forceinline__ void cp_commit() {
    asm volatile("cp.async.commit_group;" ::: "memory");
}
__device__ __forceinline__ void cp_wait1() {
    asm volatile("cp.async.wait_group 1;" ::: "memory");
}

// accurate tanh: (e^{2x}-1)/(e^{2x}+1), clamped to avoid inf/inf
__device__ __forceinline__ float ftanh(float x) {
    x = fminf(fmaxf(x, -15.0f), 15.0f);
    float e = __expf(2.0f * x);
    return __fdividef(e - 1.0f, e + 1.0f);
}

// padded index for z1s/z2s: +4 floats once we cross the half boundary
// keeps the two concurrent per-half broadcast LDS addresses on disjoint banks
__device__ __forceinline__ int zpad(int k) { return k + ((k >> 5) << 2); }

__global__ void __launch_bounds__(NTHREADS, 1) node_scan_kernel(
    const float* __restrict__ U,
    const float* __restrict__ W1, const float* __restrict__ b1,
    const float* __restrict__ W2, const float* __restrict__ b2,
    const float* __restrict__ W3, const float* __restrict__ b3,
    const float* __restrict__ wd, const float* __restrict__ bd,
    const float* __restrict__ wt, const float* __restrict__ bt,
    const float* __restrict__ wc, const float* __restrict__ bc,
    const float* __restrict__ h0,
    float* __restrict__ out, int T)
{
    __shared__ __align__(16) float ubuf[2][CHUNK * UDIM];
    __shared__ __align__(16) float z1s[72];      // 64 + pad
    __shared__ __align__(16) float z2s[72];
    __shared__ __align__(16) double sumz2[HID];

    const int tid  = threadIdx.x;
    const int w    = tid >> 5;
    const int lane = tid & 31;
    const int half = lane >> 4;          // 0: k in [0,32), 1: k in [32,64)
    const int n    = w * 16 + (lane & 15);   // owned output neuron, 0..63
    const int hk   = half * 32;              // k-base of this thread's half
    const float dt = 5.0f / 60.0f;
    const int n_chunks = (T + CHUNK - 1) / CHUNK;

    auto copy_chunk = [&](int cc) {
        if (cc >= n_chunks) return;
        const int t0 = cc * CHUNK;
        const int nf = min(CHUNK, T - t0) * UDIM;
        const float* src = U + t0 * UDIM;
        float* dst = ubuf[cc & 1];
        const int nv = nf >> 2;
        for (int i = tid; i < nv; i += NTHREADS) cp16(smem_u32(dst + 4 * i), src + 4 * i);
        for (int i = (nv << 2) + tid; i < nf; i += NTHREADS) cp4(smem_u32(dst + i), src + i);
    };
    copy_chunk(0); cp_commit();
    copy_chunk(1); cp_commit();

    // ---------------- prologue (overlaps with cp.async in flight) ----------------
    float w2r[32], Mr[32], w1u[UDIM];
    float s, comp = 0.0f, du = 0.0f;
    float binit, cinit;          // per-half init terms (b2 / dt*W1h@b3, added once)
    {
        float w1h[HDIM];
        #pragma unroll
        for (int i = 0; i < HDIM; i++) w1h[i] = W1[n * XDIM + i];
        #pragma unroll
        for (int i = 0; i < UDIM; i++) w1u[i] = W1[n * XDIM + HDIM + i];
        #pragma unroll
        for (int j = 0; j < 32; j++) w2r[j] = W2[n * HID + hk + j];
        binit = half ? 0.0f : b2[n];
        // M = dt * (W1h @ W3), this thread's half of row n
        #pragma unroll 4
        for (int j = 0; j < 32; j++) {
            float m = 0.0f;
            #pragma unroll
            for (int i = 0; i < HDIM; i++) m = fmaf(w1h[i], W3[i * HID + hk + j], m);
            Mr[j] = dt * m;
        }
        float cdt = 0.0f;
        #pragma unroll
        for (int i = 0; i < HDIM; i++) cdt = fmaf(w1h[i], b3[i], cdt);
        cinit = half ? 0.0f : dt * cdt;
        // s_0 = W1h @ h0 + b1 (both halves compute identically)
        s = b1[n];
        #pragma unroll
        for (int i = 0; i < HDIM; i++) s = fmaf(w1h[i], h0[i], s);
    }

    // readout lanes: warp 1->delay, warp 2->taxi, warp 3->loglam; lanes 0..3 quarter-dots
    const bool is_ro = (w >= 1) && (lane < 4);
    float rv[16];
    float r_sc = 0.0f, r_comp = 0.0f, r_c = 0.0f;
    float* outp = nullptr;
    int ro_base = 0;
    if (is_ro) {
        const int idx = w - 1;
        const int rq = lane;                     // quarter 0..3, k in [16q,16q+16)
        const float* wsel = (idx == 0) ? wd : (idx == 1) ? wt : wc;
        float ws[HDIM];
        #pragma unroll
        for (int i = 0; i < HDIM; i++) ws[i] = wsel[i];
        const int kb = rq * 16;
        #pragma unroll 4
        for (int j = 0; j < 16; j++) {
            float m = 0.0f;
            #pragma unroll
            for (int i = 0; i < HDIM; i++) m = fmaf(ws[i], W3[i * HID + kb + j], m);
            rv[j] = dt * m;
        }
        ro_base = zpad(kb);
        if (rq == 0) {
            r_sc = (idx == 0) ? bd[0] : (idx == 1) ? bt[0] : bc[0];
            #pragma unroll
            for (int i = 0; i < HDIM; i++) r_sc = fmaf(ws[i], h0[i], r_sc);
            float ro = 0.0f;
            #pragma unroll
            for (int i = 0; i < HDIM; i++) ro = fmaf(ws[i], b3[i], ro);
            r_c = dt * ro;
            outp = out + idx * T;
        }
    }

    double accz2 = 0.0;

    // ---------------- main loop: 2 barriers per step ----------------
    for (int c = 0; c < n_chunks; c++) {
        cp_wait1();
        __syncthreads();                       // chunk data visible
        const int nst = min(CHUNK, T - c * CHUNK);
        const float* ub = ubuf[c & 1];
        const int tbase = c * CHUNK;

        {   // du for first step of this chunk
            const float* up = ub;
            float d0 = w1u[0] * up[0], d1 = w1u[1] * up[1];
            d0 = fmaf(w1u[2], up[2], d0); d1 = fmaf(w1u[3], up[3], d1);
            d0 = fmaf(w1u[4], up[4], d0); d1 = fmaf(w1u[5], up[5], d1);
            d0 = fmaf(w1u[6], up[6], d0);
            du = d0 + d1;
        }

        for (int k = 0; k < nst; k++) {
            // ---- phase 1: z1 = tanh(s + du); readouts on prev z2 (warps 1-3) ----
            {
                float z1 = ftanh(s + du);
                if (half == 0) z1s[zpad(n)] = z1;
            }
            if (is_ro) {
                const float4* zp = (const float4*)(z2s + ro_base);
                float p0 = 0.0f, p1 = 0.0f, p2 = 0.0f, p3 = 0.0f;
                #pragma unroll
                for (int j = 0; j < 4; j++) {
                    float4 v = zp[j];
                    p0 = fmaf(rv[4 * j + 0], v.x, p0);
                    p1 = fmaf(rv[4 * j + 1], v.y, p1);
                    p2 = fmaf(rv[4 * j + 2], v.z, p2);
                    p3 = fmaf(rv[4 * j + 3], v.w, p3);
                }
                float p = (p0 + p1) + (p2 + p3);
                p += __shfl_xor_sync(0xF, p, 2);
                p += __shfl_xor_sync(0xF, p, 1);
                if (lane == 0) {
                    const int t = tbase + k;
                    if (t > 0) {                 // r_t = r_{t-1} + rv@z2_{t-1} + c (Kahan)
                        float y = (p + r_c) - r_comp;
                        float tt = r_sc + y;
                        r_comp = (tt - r_sc) - y;
                        r_sc = tt;
                    }
                    outp[t] = r_sc;
                }
            }
            if (k + 1 < nst) {                   // prefetch next du off the chain
                const float* up = ub + (k + 1) * UDIM;
                float d0 = w1u[0] * up[0], d1 = w1u[1] * up[1];
                d0 = fmaf(w1u[2], up[2], d0); d1 = fmaf(w1u[3], up[3], d1);
                d0 = fmaf(w1u[4], up[4], d0); d1 = fmaf(w1u[5], up[5], d1);
                d0 = fmaf(w1u[6], up[6], d0);
                du = d0 + d1;
            }
            __syncthreads();                     // bar1: z1s ready

            // ---- phase 2: z2 = tanh(W2 @ z1 + b2), half-dot + shfl combine ----
            {
                const float4* z1p = (const float4*)(z1s + half * 36);
                float a0 = binit, a1 = 0.0f, a2 = 0.0f, a3 = 0.0f;
                #pragma unroll
                for (int j = 0; j < 8; j++) {
                    float4 v = z1p[j];
                    a0 = fmaf(w2r[4 * j + 0], v.x, a0);
                    a1 = fmaf(w2r[4 * j + 1], v.y, a1);
                    a2 = fmaf(w2r[4 * j + 2], v.z, a2);
                    a3 = fmaf(w2r[4 * j + 3], v.w, a3);
                }
                float pre = (a0 + a1) + (a2 + a3);
                pre += __shfl_xor_sync(0xffffffff, pre, 16);
                float z2 = ftanh(pre);
                if (half == 0) {
                    z2s[zpad(n)] = z2;
                    accz2 += (double)z2;         // exact hT reconstruction data
                }
            }
            __syncthreads();                     // bar2: z2s ready

            // ---- phase 3: s += dt*(W1h@W3)@z2 + dt*W1h@b3, Kahan-compensated ----
            {
                const float4* z2p = (const float4*)(z2s + half * 36);
                float c0 = cinit, c1 = 0.0f, c2 = 0.0f, c3 = 0.0f;
                #pragma unroll
                for (int j = 0; j < 8; j++) {
                    float4 v = z2p[j];
                    c0 = fmaf(Mr[4 * j + 0], v.x, c0);
                    c1 = fmaf(Mr[4 * j + 1], v.y, c1);
                    c2 = fmaf(Mr[4 * j + 2], v.z, c2);
                    c3 = fmaf(Mr[4 * j + 3], v.w, c3);
                }
                float delta = (c0 + c1) + (c2 + c3);
                delta += __shfl_xor_sync(0xffffffff, delta, 16);
                float y = delta - comp;
                float tt = s + y;
                comp = (tt - s) - y;
                s = tt;
            }
            // no 3rd barrier: next writes to z1s/z2s are fenced by bar2/bar1'
        }
        copy_chunk(c + 2);
        cp_commit();
    }

    // ---------------- finalize hT = h0 + dt*(W3 @ sum(z2) + T*b3) in fp64 ----------------
    __syncthreads();
    if (half == 0) sumz2[n] = accz2;
    __syncthreads();
    if (tid < HDIM) {
        double acc = (double)T * (double)b3[tid];
        #pragma unroll 8
        for (int j = 0; j < HID; j++)
            acc += (double)W3[tid * HID + j] * sumz2[j];
        out[3 * T + tid] = (float)((double)h0[tid] + (double)dt * acc);
    }
}

extern "C" void kernel_launch(void* const* d_in, const int* in_sizes, int n_in,
                              void* d_out, int out_size)
{
    const int T = in_sizes[0] / UDIM;
    node_scan_kernel<<<1, NTHREADS>>>(
        (const float*)d_in[0],                          // U
        (const float*)d_in[1], (const float*)d_in[2],   // W1, b1
        (const float*)d_in[3], (const float*)d_in[4],   // W2, b2
        (const float*)d_in[5], (const float*)d_in[6],   // W3, b3
        (const float*)d_in[7], (const float*)d_in[8],   // wd, bd
        (const float*)d_in[9], (const float*)d_in[10],  // wt, bt
        (const float*)d_in[11], (const float*)d_in[12], // wc, bc
        (const float*)d_in[13],                         // h0
        (float*)d_out, T);
}

// round 11
// speedup vs baseline: 1.3654x; 1.3654x over previous
#include <cuda_runtime.h>
#include <cuda_bf16.h>

#define HDIM 16
#define UDIM 7
#define HID  64
#define XDIM 23
#define CHUNK 512
#define NTHREADS 96

__device__ __forceinline__ unsigned smem_u32(const void* p) {
    return (unsigned)__cvta_generic_to_shared(p);
}
__device__ __forceinline__ void cp16(unsigned dst, const void* src) {
    asm volatile("cp.async.cg.shared.global [%0], [%1], 16;" :: "r"(dst), "l"(src));
}
__device__ __forceinline__ void cp4(unsigned dst, const void* src) {
    asm volatile("cp.async.ca.shared.global [%0], [%1], 4;" :: "r"(dst), "l"(src));
}
__device__ __forceinline__ void cp_commit() {
    asm volatile("cp.async.commit_group;" ::: "memory");
}
__device__ __forceinline__ void cp_wait1() {
    asm volatile("cp.async.wait_group 1;" ::: "memory");
}

// accurate tanh: (e^{2x}-1)/(e^{2x}+1), clamped to avoid inf/inf
__device__ __forceinline__ float ftanh(float x) {
    x = fminf(fmaxf(x, -15.0f), 15.0f);
    float e = __expf(2.0f * x);
    return __fdividef(e - 1.0f, e + 1.0f);
}

// 64-wide dot: 64 register weights x 64 floats in 16B-aligned smem (broadcast reads)
__device__ __forceinline__ float dot64(const float* __restrict__ wr,
                                       const float* __restrict__ zs, float init) {
    const float4* zp = (const float4*)zs;
    float a0 = init, a1 = 0.0f, a2 = 0.0f, a3 = 0.0f;
    #pragma unroll
    for (int j = 0; j < 16; j++) {
        float4 v = zp[j];
        a0 = fmaf(wr[4 * j + 0], v.x, a0);
        a1 = fmaf(wr[4 * j + 1], v.y, a1);
        a2 = fmaf(wr[4 * j + 2], v.z, a2);
        a3 = fmaf(wr[4 * j + 3], v.w, a3);
    }
    return (a0 + a1) + (a2 + a3);
}

__device__ __forceinline__ float du7(const float* __restrict__ w1u,
                                     const float* __restrict__ up) {
    float d0 = w1u[0] * up[0], d1 = w1u[1] * up[1];
    d0 = fmaf(w1u[2], up[2], d0); d1 = fmaf(w1u[3], up[3], d1);
    d0 = fmaf(w1u[4], up[4], d0); d1 = fmaf(w1u[5], up[5], d1);
    d0 = fmaf(w1u[6], up[6], d0);
    return d0 + d1;
}

__global__ void __launch_bounds__(NTHREADS, 1) node_scan_kernel(
    const float* __restrict__ U,
    const float* __restrict__ W1, const float* __restrict__ b1,
    const float* __restrict__ W2, const float* __restrict__ b2,
    const float* __restrict__ W3, const float* __restrict__ b3,
    const float* __restrict__ wd, const float* __restrict__ bd,
    const float* __restrict__ wt, const float* __restrict__ bt,
    const float* __restrict__ wc, const float* __restrict__ bc,
    const float* __restrict__ h0,
    float* __restrict__ out, int T)
{
    __shared__ __align__(16) float ubuf[2][CHUNK * UDIM];
    __shared__ __align__(16) float z1s[HID];
    __shared__ __align__(16) float z2s[HID];
    __shared__ __align__(16) double sumz2[HID];

    const int tid = threadIdx.x;
    const float dt = 5.0f / 60.0f;
    const int n_chunks = (T + CHUNK - 1) / CHUNK;

    const bool is_s  = (tid < HID);            // warps 0,1: neuron tid
    const bool is_ro = (tid >= HID) && (tid < HID + 3);   // warp 2 lanes 0..2

    auto copy_chunk = [&](int cc) {
        if (cc >= n_chunks) return;
        const int t0 = cc * CHUNK;
        const int nf = min(CHUNK, T - t0) * UDIM;
        const float* src = U + t0 * UDIM;
        float* dst = ubuf[cc & 1];
        const int nv = nf >> 2;
        for (int i = tid; i < nv; i += NTHREADS) cp16(smem_u32(dst + 4 * i), src + 4 * i);
        for (int i = (nv << 2) + tid; i < nf; i += NTHREADS) cp4(smem_u32(dst + i), src + i);
    };
    copy_chunk(0); cp_commit();
    copy_chunk(1); cp_commit();

    // ---------------- prologue (overlaps the in-flight cp.async) ----------------
    // Role-shared arrays: A = P1 dot weights (dt*W1h@W3 row  OR  dt*W3^T@w_sel),
    //                     B = W2 row (s-threads only).
    float A[HID], B[HID], w1u[UDIM];
    float state = 0.0f, comp = 0.0f, du = 0.0f, cinit = 0.0f, b2r = 0.0f;
    float* outp = nullptr;
    double accz2 = 0.0;

    if (is_s) {
        const int n = tid;
        float w1h[HDIM];
        #pragma unroll
        for (int i = 0; i < HDIM; i++) w1h[i] = W1[n * XDIM + i];
        #pragma unroll
        for (int i = 0; i < UDIM; i++) w1u[i] = W1[n * XDIM + HDIM + i];
        #pragma unroll
        for (int j = 0; j < HID; j++) B[j] = W2[n * HID + j];
        b2r = b2[n];
        // A = dt * (W1h @ W3) row n
        #pragma unroll 4
        for (int j = 0; j < HID; j++) {
            float m = 0.0f;
            #pragma unroll
            for (int i = 0; i < HDIM; i++) m = fmaf(w1h[i], W3[i * HID + j], m);
            A[j] = dt * m;
        }
        float cd = 0.0f;
        #pragma unroll
        for (int i = 0; i < HDIM; i++) cd = fmaf(w1h[i], b3[i], cd);
        cinit = dt * cd;
        // state = s_0 - cinit  (uniform "add cinit every step" incl. t=0 w/ z2s=0)
        float s0 = b1[n];
        #pragma unroll
        for (int i = 0; i < HDIM; i++) s0 = fmaf(w1h[i], h0[i], s0);
        state = s0 - cinit;
        z2s[n] = 0.0f;
    } else {
        #pragma unroll
        for (int j = 0; j < HID; j++) { A[j] = 0.0f; B[j] = 0.0f; }
        #pragma unroll
        for (int i = 0; i < UDIM; i++) w1u[i] = 0.0f;
        if (is_ro) {
            const int idx = tid - HID;
            const float* wsel = (idx == 0) ? wd : (idx == 1) ? wt : wc;
            const float bsel  = (idx == 0) ? bd[0] : (idx == 1) ? bt[0] : bc[0];
            float ws[HDIM];
            #pragma unroll
            for (int i = 0; i < HDIM; i++) ws[i] = wsel[i];
            #pragma unroll 4
            for (int j = 0; j < HID; j++) {
                float m = 0.0f;
                #pragma unroll
                for (int i = 0; i < HDIM; i++) m = fmaf(ws[i], W3[i * HID + j], m);
                A[j] = dt * m;
            }
            float rc = 0.0f;
            #pragma unroll
            for (int i = 0; i < HDIM; i++) rc = fmaf(ws[i], b3[i], rc);
            cinit = dt * rc;
            float r0 = bsel;
            #pragma unroll
            for (int i = 0; i < HDIM; i++) r0 = fmaf(ws[i], h0[i], r0);
            state = r0 - cinit;
            outp = out + idx * T;
        }
    }

    // ---------------- main loop: 2 barriers per step ----------------
    for (int c = 0; c < n_chunks; c++) {
        cp_wait1();
        __syncthreads();                       // chunk data visible; z2s/prologue visible
        const int nst = min(CHUNK, T - c * CHUNK);
        const float* ub = ubuf[c & 1];
        const int tbase = c * CHUNK;

        if (is_s) du = du7(w1u, ub);           // du for first step of chunk

        for (int k = 0; k < nst; k++) {
            // ---- P1: linear recurrence step off z2_{t-1} (all roles, same code) ----
            {
                float delta = dot64(A, z2s, cinit);
                float y = delta - comp;        // Kahan-compensated accumulate
                float t2 = state + y;
                comp = (t2 - state) - y;
                state = t2;
            }
            if (is_s) {
                z1s[tid] = ftanh(state + du);  // z1_t
                if (k + 1 < nst) du = du7(w1u, ub + (k + 1) * UDIM);
            } else if (is_ro) {
                outp[tbase + k] = state;       // r_t = wsel @ h_t + b  (pre-update h)
            }
            __syncthreads();                   // bar1: z1s ready; z2s reads done

            // ---- P2: z2_t = tanh(W2 @ z1_t + b2) ----
            if (is_s) {
                float z2 = ftanh(dot64(B, z1s, b2r));
                z2s[tid] = z2;
                accz2 += (double)z2;           // for exact hT reconstruction
            }
            __syncthreads();                   // bar2: z2s ready; z1s reads done
        }
        copy_chunk(c + 2);
        cp_commit();
    }

    // ---------------- finalize hT = h0 + dt*(W3 @ sum(z2) + T*b3) in fp64 ----------------
    __syncthreads();
    if (is_s) sumz2[tid] = accz2;
    __syncthreads();
    if (tid < HDIM) {
        double acc = (double)T * (double)b3[tid];
        #pragma unroll 8
        for (int j = 0; j < HID; j++)
            acc += (double)W3[tid * HID + j] * sumz2[j];
        out[3 * T + tid] = (float)((double)h0[tid] + (double)dt * acc);
    }
}

extern "C" void kernel_launch(void* const* d_in, const int* in_sizes, int n_in,
                              void* d_out, int out_size)
{
    const int T = in_sizes[0] / UDIM;
    node_scan_kernel<<<1, NTHREADS>>>(
        (const float*)d_in[0],                          // U
        (const float*)d_in[1], (const float*)d_in[2],   // W1, b1
        (const float*)d_in[3], (const float*)d_in[4],   // W2, b2
        (const float*)d_in[5], (const float*)d_in[6],   // W3, b3
        (const float*)d_in[7], (const float*)d_in[8],   // wd, bd
        (const float*)d_in[9], (const float*)d_in[10],  // wt, bt
        (const float*)d_in[11], (const float*)d_in[12], // wc, bc
        (const float*)d_in[13],                         // h0
        (float*)d_out, T);
}